// round 1
// baseline (speedup 1.0000x reference)
#include <cuda_runtime.h>
#include <math.h>

#define NB      8
#define SEQ     1024
#define DIM     512
#define NHEADS  8
#define DHEAD   64
#define INNER   512
#define M_TOT   (NB*SEQ)        /* 8192 */
#define BH      (NB*NHEADS)     /* 64 */

// ---- scratch (allocation-free: __device__ globals) ----
__device__ float g_q [(size_t)BH*SEQ*DHEAD];   // 16 MB, layout [bh][n][d]
__device__ float g_k [(size_t)BH*SEQ*DHEAD];   // 16 MB
__device__ float g_v [(size_t)BH*SEQ*DHEAD];   // 16 MB
__device__ float g_ao[(size_t)M_TOT*INNER];    // 16 MB, layout [b*n][h*d]

// ============================================================================
// GEMM1: C = x[8192,512] @ w_qkv[512,1536], fused epilogue scatters into
// g_q/g_k/g_v with [bh][n][d] layout. 128x128x16 tile, 8x8 per thread.
// ============================================================================
__global__ __launch_bounds__(256) void qkv_gemm_kernel(const float* __restrict__ A,
                                                       const float* __restrict__ W)
{
    __shared__ float As[128][16];
    __shared__ float Bs[16][128];
    const int tx   = threadIdx.x;
    const int row0 = blockIdx.y * 128;
    const int col0 = blockIdx.x * 128;
    const int tr   = tx >> 4;   // 0..15
    const int tc   = tx & 15;   // 0..15

    float acc[8][8];
#pragma unroll
    for (int i = 0; i < 8; i++)
#pragma unroll
        for (int j = 0; j < 8; j++) acc[i][j] = 0.f;

    for (int k0 = 0; k0 < DIM; k0 += 16) {
#pragma unroll
        for (int t = 0; t < 2; t++) {           // A tile: 128x16
            int id = tx + t * 256;
            int r = id >> 2, c = (id & 3) << 2;
            *(float4*)&As[r][c] =
                *(const float4*)&A[(size_t)(row0 + r) * DIM + k0 + c];
        }
#pragma unroll
        for (int t = 0; t < 2; t++) {           // B tile: 16x128
            int id = tx + t * 256;
            int r = id >> 5, c = (id & 31) << 2;
            *(float4*)&Bs[r][c] =
                *(const float4*)&W[(size_t)(k0 + r) * (3 * INNER) + col0 + c];
        }
        __syncthreads();
#pragma unroll
        for (int kk = 0; kk < 16; kk++) {
            float a[8], b[8];
#pragma unroll
            for (int i = 0; i < 8; i++) a[i] = As[tr * 8 + i][kk];
#pragma unroll
            for (int j = 0; j < 8; j++) b[j] = Bs[kk][tc * 8 + j];
#pragma unroll
            for (int i = 0; i < 8; i++)
#pragma unroll
                for (int j = 0; j < 8; j++)
                    acc[i][j] = fmaf(a[i], b[j], acc[i][j]);
        }
        __syncthreads();
    }

    // Epilogue: column block of 8 stays within one head (8 | 64) and one of
    // q/k/v (8 | 512), so which/h/d are constant across j.
    const int c_base = col0 + tc * 8;
    const int which  = c_base >> 9;
    const int inner  = c_base & 511;
    const int h      = inner >> 6;
    const int d      = inner & 63;
    float* dstbuf = (which == 0) ? g_q : (which == 1) ? g_k : g_v;
#pragma unroll
    for (int i = 0; i < 8; i++) {
        int m  = row0 + tr * 8 + i;
        int b_ = m >> 10, n = m & 1023;
        size_t off = ((size_t)((b_ * NHEADS + h) * SEQ + n)) * DHEAD + d;
        *(float4*)&dstbuf[off]     = make_float4(acc[i][0], acc[i][1], acc[i][2], acc[i][3]);
        *(float4*)&dstbuf[off + 4] = make_float4(acc[i][4], acc[i][5], acc[i][6], acc[i][7]);
    }
}

// ============================================================================
// Attention: flash-style, 1 thread = 1 query row. Block = 128 threads
// (128 queries), grid = (8 q-tiles, 64 bh). K/V tiles of 32 keys in smem,
// scores staged in padded smem so the online-softmax correction is per-tile.
// Diagonal is masked to -inf (exp -> exactly 0, matching the reference).
// ============================================================================
__global__ __launch_bounds__(128) void attn_kernel(const float* __restrict__ temp)
{
    __shared__ float Ks[32][64];
    __shared__ float Vs[32][64];
    __shared__ float Ss[128][33];   // padded: conflict-free column writes

    const int bh  = blockIdx.y;
    const int tid = threadIdx.x;
    const int qi  = blockIdx.x * 128 + tid;
    const float scale = expf(*temp);

    const float* Q  = g_q + (size_t)bh * SEQ * DHEAD;
    const float* Kp = g_k + (size_t)bh * SEQ * DHEAD;
    const float* Vp = g_v + (size_t)bh * SEQ * DHEAD;

    float4 q[16];
#pragma unroll
    for (int i = 0; i < 16; i++) {
        q[i] = *(const float4*)&Q[(size_t)qi * DHEAD + i * 4];
        q[i].x *= scale; q[i].y *= scale; q[i].z *= scale; q[i].w *= scale;
    }
    float4 acc[16];
#pragma unroll
    for (int i = 0; i < 16; i++) acc[i] = make_float4(0.f, 0.f, 0.f, 0.f);
    float mrow = -INFINITY, lrow = 0.f;

    for (int k0 = 0; k0 < SEQ; k0 += 32) {
#pragma unroll
        for (int t = 0; t < 4; t++) {
            int id = tid + t * 128;
            int r = id >> 4, c = (id & 15) << 2;
            *(float4*)&Ks[r][c] = *(const float4*)&Kp[(size_t)(k0 + r) * DHEAD + c];
            *(float4*)&Vs[r][c] = *(const float4*)&Vp[(size_t)(k0 + r) * DHEAD + c];
        }
        __syncthreads();

        float mtile = -INFINITY;
#pragma unroll 4
        for (int j = 0; j < 32; j++) {
            float s = 0.f;
#pragma unroll
            for (int i = 0; i < 16; i++) {
                float4 kv = *(const float4*)&Ks[j][i * 4];
                s += q[i].x * kv.x + q[i].y * kv.y + q[i].z * kv.z + q[i].w * kv.w;
            }
            if (k0 + j == qi) s = -INFINITY;    // self-mask
            mtile = fmaxf(mtile, s);
            Ss[tid][j] = s;
        }

        float mnew = fmaxf(mrow, mtile);
        float corr = __expf(mrow - mnew);       // exp(-inf)=0 on first tile
        lrow *= corr;
#pragma unroll
        for (int i = 0; i < 16; i++) {
            acc[i].x *= corr; acc[i].y *= corr; acc[i].z *= corr; acc[i].w *= corr;
        }
        mrow = mnew;

#pragma unroll 4
        for (int j = 0; j < 32; j++) {
            float p = __expf(Ss[tid][j] - mnew);
            lrow += p;
#pragma unroll
            for (int i = 0; i < 16; i++) {
                float4 vv = *(const float4*)&Vs[j][i * 4];
                acc[i].x = fmaf(p, vv.x, acc[i].x);
                acc[i].y = fmaf(p, vv.y, acc[i].y);
                acc[i].z = fmaf(p, vv.z, acc[i].z);
                acc[i].w = fmaf(p, vv.w, acc[i].w);
            }
        }
        __syncthreads();
    }

    const float inv = 1.f / lrow;
    const int b_ = bh >> 3, h = bh & 7;
    float* dst = g_ao + ((size_t)(b_ * SEQ + qi)) * INNER + h * DHEAD;
#pragma unroll
    for (int i = 0; i < 16; i++) {
        float4 o = acc[i];
        o.x *= inv; o.y *= inv; o.z *= inv; o.w *= inv;
        *(float4*)&dst[i * 4] = o;
    }
}

// ============================================================================
// GEMM3: d_out = g_ao[8192,512] @ w_out[512,512]
// ============================================================================
__global__ __launch_bounds__(256) void out_gemm_kernel(const float* __restrict__ W,
                                                       float* __restrict__ C)
{
    __shared__ float As[128][16];
    __shared__ float Bs[16][128];
    const int tx   = threadIdx.x;
    const int row0 = blockIdx.y * 128;
    const int col0 = blockIdx.x * 128;
    const int tr   = tx >> 4;
    const int tc   = tx & 15;

    float acc[8][8];
#pragma unroll
    for (int i = 0; i < 8; i++)
#pragma unroll
        for (int j = 0; j < 8; j++) acc[i][j] = 0.f;

    for (int k0 = 0; k0 < INNER; k0 += 16) {
#pragma unroll
        for (int t = 0; t < 2; t++) {
            int id = tx + t * 256;
            int r = id >> 2, c = (id & 3) << 2;
            *(float4*)&As[r][c] =
                *(const float4*)&g_ao[(size_t)(row0 + r) * INNER + k0 + c];
        }
#pragma unroll
        for (int t = 0; t < 2; t++) {
            int id = tx + t * 256;
            int r = id >> 5, c = (id & 31) << 2;
            *(float4*)&Bs[r][c] =
                *(const float4*)&W[(size_t)(k0 + r) * DIM + col0 + c];
        }
        __syncthreads();
#pragma unroll
        for (int kk = 0; kk < 16; kk++) {
            float a[8], b[8];
#pragma unroll
            for (int i = 0; i < 8; i++) a[i] = As[tr * 8 + i][kk];
#pragma unroll
            for (int j = 0; j < 8; j++) b[j] = Bs[kk][tc * 8 + j];
#pragma unroll
            for (int i = 0; i < 8; i++)
#pragma unroll
                for (int j = 0; j < 8; j++)
                    acc[i][j] = fmaf(a[i], b[j], acc[i][j]);
        }
        __syncthreads();
    }

#pragma unroll
    for (int i = 0; i < 8; i++) {
        int m = row0 + tr * 8 + i;
        size_t off = (size_t)m * DIM + col0 + tc * 8;
        *(float4*)&C[off]     = make_float4(acc[i][0], acc[i][1], acc[i][2], acc[i][3]);
        *(float4*)&C[off + 4] = make_float4(acc[i][4], acc[i][5], acc[i][6], acc[i][7]);
    }
}

// ============================================================================
extern "C" void kernel_launch(void* const* d_in, const int* in_sizes, int n_in,
                              void* d_out, int out_size)
{
    // Identify inputs by element count (robust to ordering):
    // x: 8*1024*512 = 4194304, w_qkv: 512*1536 = 786432,
    // w_out: 512*512 = 262144, temperature: 1
    const float* x    = nullptr;
    const float* wqkv = nullptr;
    const float* wout = nullptr;
    const float* temp = nullptr;
    for (int i = 0; i < n_in; i++) {
        switch (in_sizes[i]) {
            case 4194304: x    = (const float*)d_in[i]; break;
            case 786432:  wqkv = (const float*)d_in[i]; break;
            case 262144:  wout = (const float*)d_in[i]; break;
            case 1:       temp = (const float*)d_in[i]; break;
            default: break;
        }
    }
    float* out = (float*)d_out;

    qkv_gemm_kernel<<<dim3(12, 64), 256>>>(x, wqkv);   // 1536/128, 8192/128
    attn_kernel<<<dim3(8, 64), 128>>>(temp);           // 1024/128 q-tiles, 64 bh
    out_gemm_kernel<<<dim3(4, 64), 256>>>(wout, out);  // 512/128, 8192/128
    (void)out_size;
}

// round 3
// speedup vs baseline: 1.3590x; 1.3590x over previous
#include <cuda_runtime.h>
#include <cuda_bf16.h>
#include <math.h>
#include <stdint.h>

#define NB      8
#define SEQ     1024
#define DIM     512
#define NHEADS  8
#define DHEAD   64
#define INNER   512
#define M_TOT   (NB*SEQ)        /* 8192 */
#define BH      (NB*NHEADS)     /* 64 */

// ---- scratch (allocation-free: __device__ globals) ----
__device__ float g_q [(size_t)BH*SEQ*DHEAD];   // [bh][n][d]
__device__ float g_k [(size_t)BH*SEQ*DHEAD];
__device__ float g_v [(size_t)BH*SEQ*DHEAD];
__device__ float g_ao[(size_t)M_TOT*INNER];    // [b*n][h*d]
// pre-transposed + split weights: [n][k] bf16
__device__ __nv_bfloat16 g_wqkv_hi[(size_t)3*INNER*DIM];
__device__ __nv_bfloat16 g_wqkv_lo[(size_t)3*INNER*DIM];
__device__ __nv_bfloat16 g_wout_hi[(size_t)DIM*INNER];
__device__ __nv_bfloat16 g_wout_lo[(size_t)DIM*INNER];

// ========================== mma/ldmatrix helpers ===========================
__device__ __forceinline__ uint32_t smem_u32(const void* p) {
    uint32_t a;
    asm("{ .reg .u64 t; cvta.to.shared.u64 t, %1; cvt.u32.u64 %0, t; }" : "=r"(a) : "l"(p));
    return a;
}
__device__ __forceinline__ void ldm_x4(uint32_t* f, uint32_t addr) {
    asm volatile("ldmatrix.sync.aligned.m8n8.x4.shared.b16 {%0,%1,%2,%3}, [%4];"
                 : "=r"(f[0]), "=r"(f[1]), "=r"(f[2]), "=r"(f[3]) : "r"(addr));
}
__device__ __forceinline__ void mma_bf16(float* d, const uint32_t* a, const uint32_t* b) {
    asm volatile("mma.sync.aligned.m16n8k16.row.col.f32.bf16.bf16.f32 "
                 "{%0,%1,%2,%3}, {%4,%5,%6,%7}, {%8,%9}, {%0,%1,%2,%3};"
                 : "+f"(d[0]), "+f"(d[1]), "+f"(d[2]), "+f"(d[3])
                 : "r"(a[0]), "r"(a[1]), "r"(a[2]), "r"(a[3]), "r"(b[0]), "r"(b[1]));
}
__device__ __forceinline__ uint32_t pack_hi(float x, float y) {
    __nv_bfloat162 h = {__float2bfloat16(x), __float2bfloat16(y)};
    return *(uint32_t*)&h;
}
__device__ __forceinline__ uint32_t pack_lo(float x, float y) {
    float rx = x - __bfloat162float(__float2bfloat16(x));
    float ry = y - __bfloat162float(__float2bfloat16(y));
    __nv_bfloat162 l = {__float2bfloat16(rx), __float2bfloat16(ry)};
    return *(uint32_t*)&l;
}

// ============================================================================
// Weight prep: transpose [512][N] fp32 -> [N][512] bf16 (hi, lo split)
// ============================================================================
__global__ void wsplit_kernel(const float* __restrict__ W,
                              __nv_bfloat16* __restrict__ hi,
                              __nv_bfloat16* __restrict__ lo, int N)
{
    __shared__ float t[32][33];
    int n = blockIdx.x * 32 + threadIdx.x;
    int k = blockIdx.y * 32 + threadIdx.y;
    t[threadIdx.y][threadIdx.x] = W[(size_t)k * N + n];
    __syncthreads();
    int n2 = blockIdx.x * 32 + threadIdx.y;
    int k2 = blockIdx.y * 32 + threadIdx.x;
    float v = t[threadIdx.x][threadIdx.y];
    __nv_bfloat16 h = __float2bfloat16(v);
    hi[(size_t)n2 * DIM + k2] = h;
    lo[(size_t)n2 * DIM + k2] = __float2bfloat16(v - __bfloat162float(h));
}

// ============================================================================
// HMMA GEMM: C[M_TOT, Ntot] = A[M_TOT, 512] @ B^T, B pre-split [n][512] bf16.
// CTA tile 128x128, BK=32; 8 warps (4 M x 2 N), warp tile 32x64.
// Split-bf16 3-MMA accumulation in fp32 (hh + hl + lh).
// mode 0: scatter into g_q/g_k/g_v ([bh][n][d]); mode 1: direct store to C.
// ============================================================================
#define BK  32
#define PAD 40   /* bf16 row stride: 80B -> conflict-free ldmatrix */

__global__ __launch_bounds__(256) void gemm_hmma_kernel(
    const float* __restrict__ A,
    const __nv_bfloat16* __restrict__ Bhi,
    const __nv_bfloat16* __restrict__ Blo,
    float* __restrict__ C, int mode)
{
    __shared__ __nv_bfloat16 sAhi[128 * PAD];
    __shared__ __nv_bfloat16 sAlo[128 * PAD];
    __shared__ __nv_bfloat16 sBhi[128 * PAD];
    __shared__ __nv_bfloat16 sBlo[128 * PAD];

    const int tx   = threadIdx.x;
    const int lane = tx & 31;
    const int wid  = tx >> 5;
    const int wm   = wid >> 1;          // 0..3 -> 32 rows each
    const int wn   = wid & 1;           // 0..1 -> 64 cols each
    const int row0 = blockIdx.y * 128;
    const int col0 = blockIdx.x * 128;

    const uint32_t uAhi = smem_u32(sAhi), uAlo = smem_u32(sAlo);
    const uint32_t uBhi = smem_u32(sBhi), uBlo = smem_u32(sBlo);

    float acc[2][8][4];
#pragma unroll
    for (int i = 0; i < 2; i++)
#pragma unroll
        for (int j = 0; j < 8; j++)
#pragma unroll
            for (int t = 0; t < 4; t++) acc[i][j][t] = 0.f;

    // precomputed ldmatrix lane addressing
    const int a_row  = lane & 15;             // row within 16
    const int a_half = lane >> 4;             // 0/1 -> +16B
    const int b_row  = (lane & 7) + ((lane >> 4) << 3);   // n-row within 16
    const int b_half = (lane >> 3) & 1;                   // k half -> +16B

    for (int kc = 0; kc < DIM; kc += BK) {
        // ---- A: load fp32, split to bf16 hi/lo, store padded smem ----
#pragma unroll
        for (int t = 0; t < 4; t++) {
            int id = tx + t * 256;             // 0..1023
            int r  = id >> 3;
            int c4 = (id & 7) << 2;
            float4 v = *(const float4*)&A[(size_t)(row0 + r) * DIM + kc + c4];
            uint2 hu = make_uint2(pack_hi(v.x, v.y), pack_hi(v.z, v.w));
            uint2 lu = make_uint2(pack_lo(v.x, v.y), pack_lo(v.z, v.w));
            int off = r * PAD + c4;
            *(uint2*)&sAhi[off] = hu;
            *(uint2*)&sAlo[off] = lu;
        }
        // ---- B: pre-split bf16, copy to padded smem ----
#pragma unroll
        for (int t = 0; t < 2; t++) {
            int id = tx + t * 256;             // 0..511
            int r  = id >> 2;
            int c8 = (id & 3) << 3;
            size_t go = (size_t)(col0 + r) * DIM + kc + c8;
            int off = r * PAD + c8;
            *(uint4*)&sBhi[off] = *(const uint4*)&Bhi[go];
            *(uint4*)&sBlo[off] = *(const uint4*)&Blo[go];
        }
        __syncthreads();

#pragma unroll
        for (int kk = 0; kk < 2; kk++) {
            uint32_t afh[2][4], afl[2][4];
#pragma unroll
            for (int mf = 0; mf < 2; mf++) {
                uint32_t boff = (uint32_t)((wm * 32 + mf * 16 + a_row) * PAD + kk * 16) * 2
                              + a_half * 16;
                ldm_x4(afh[mf], uAhi + boff);
                ldm_x4(afl[mf], uAlo + boff);
            }
            uint32_t bfh[8][2], bfl[8][2];
#pragma unroll
            for (int nf2 = 0; nf2 < 4; nf2++) {
                uint32_t boff = (uint32_t)((wn * 64 + nf2 * 16 + b_row) * PAD + kk * 16) * 2
                              + b_half * 16;
                uint32_t th[4], tl[4];
                ldm_x4(th, uBhi + boff);
                ldm_x4(tl, uBlo + boff);
                bfh[nf2*2][0] = th[0]; bfh[nf2*2][1] = th[1];
                bfh[nf2*2+1][0] = th[2]; bfh[nf2*2+1][1] = th[3];
                bfl[nf2*2][0] = tl[0]; bfl[nf2*2][1] = tl[1];
                bfl[nf2*2+1][0] = tl[2]; bfl[nf2*2+1][1] = tl[3];
            }
#pragma unroll
            for (int mf = 0; mf < 2; mf++)
#pragma unroll
                for (int nf = 0; nf < 8; nf++) {
                    mma_bf16(acc[mf][nf], afh[mf], bfh[nf]);
                    mma_bf16(acc[mf][nf], afh[mf], bfl[nf]);
                    mma_bf16(acc[mf][nf], afl[mf], bfh[nf]);
                }
        }
        __syncthreads();
    }

    // ---- epilogue ----
#pragma unroll
    for (int mf = 0; mf < 2; mf++) {
        int m_base = row0 + wm * 32 + mf * 16 + (lane >> 2);
#pragma unroll
        for (int nf = 0; nf < 8; nf++) {
            int c = col0 + wn * 64 + nf * 8 + 2 * (lane & 3);
            float2 v0 = make_float2(acc[mf][nf][0], acc[mf][nf][1]);
            float2 v1 = make_float2(acc[mf][nf][2], acc[mf][nf][3]);
            if (mode == 1) {
                *(float2*)&C[(size_t)m_base * DIM + c]       = v0;
                *(float2*)&C[(size_t)(m_base + 8) * DIM + c] = v1;
            } else {
                int which = c >> 9;
                int inner = c & 511;
                int h     = inner >> 6;
                int d     = inner & 63;
                float* buf = (which == 0) ? g_q : (which == 1) ? g_k : g_v;
                int b0 = m_base >> 10, n0 = m_base & 1023;
                *(float2*)&buf[((size_t)((b0 * NHEADS + h) * SEQ + n0)) * DHEAD + d] = v0;
                int m1 = m_base + 8;
                int b1 = m1 >> 10, n1 = m1 & 1023;
                *(float2*)&buf[((size_t)((b1 * NHEADS + h) * SEQ + n1)) * DHEAD + d] = v1;
            }
        }
    }
}

// ============================================================================
// Attention: flash-style, 1 thread = 1 query row (unchanged; R4 target).
// ============================================================================
__global__ __launch_bounds__(128) void attn_kernel(const float* __restrict__ temp)
{
    __shared__ float Ks[32][64];
    __shared__ float Vs[32][64];
    __shared__ float Ss[128][33];

    const int bh  = blockIdx.y;
    const int tid = threadIdx.x;
    const int qi  = blockIdx.x * 128 + tid;
    const float scale = expf(*temp);

    const float* Q  = g_q + (size_t)bh * SEQ * DHEAD;
    const float* Kp = g_k + (size_t)bh * SEQ * DHEAD;
    const float* Vp = g_v + (size_t)bh * SEQ * DHEAD;

    float4 q[16];
#pragma unroll
    for (int i = 0; i < 16; i++) {
        q[i] = *(const float4*)&Q[(size_t)qi * DHEAD + i * 4];
        q[i].x *= scale; q[i].y *= scale; q[i].z *= scale; q[i].w *= scale;
    }
    float4 acc[16];
#pragma unroll
    for (int i = 0; i < 16; i++) acc[i] = make_float4(0.f, 0.f, 0.f, 0.f);
    float mrow = -INFINITY, lrow = 0.f;

    for (int k0 = 0; k0 < SEQ; k0 += 32) {
#pragma unroll
        for (int t = 0; t < 4; t++) {
            int id = tid + t * 128;
            int r = id >> 4, c = (id & 15) << 2;
            *(float4*)&Ks[r][c] = *(const float4*)&Kp[(size_t)(k0 + r) * DHEAD + c];
            *(float4*)&Vs[r][c] = *(const float4*)&Vp[(size_t)(k0 + r) * DHEAD + c];
        }
        __syncthreads();

        float mtile = -INFINITY;
#pragma unroll 4
        for (int j = 0; j < 32; j++) {
            float s = 0.f;
#pragma unroll
            for (int i = 0; i < 16; i++) {
                float4 kv = *(const float4*)&Ks[j][i * 4];
                s += q[i].x * kv.x + q[i].y * kv.y + q[i].z * kv.z + q[i].w * kv.w;
            }
            if (k0 + j == qi) s = -INFINITY;
            mtile = fmaxf(mtile, s);
            Ss[tid][j] = s;
        }

        float mnew = fmaxf(mrow, mtile);
        float corr = __expf(mrow - mnew);
        lrow *= corr;
#pragma unroll
        for (int i = 0; i < 16; i++) {
            acc[i].x *= corr; acc[i].y *= corr; acc[i].z *= corr; acc[i].w *= corr;
        }
        mrow = mnew;

#pragma unroll 4
        for (int j = 0; j < 32; j++) {
            float p = __expf(Ss[tid][j] - mnew);
            lrow += p;
#pragma unroll
            for (int i = 0; i < 16; i++) {
                float4 vv = *(const float4*)&Vs[j][i * 4];
                acc[i].x = fmaf(p, vv.x, acc[i].x);
                acc[i].y = fmaf(p, vv.y, acc[i].y);
                acc[i].z = fmaf(p, vv.z, acc[i].z);
                acc[i].w = fmaf(p, vv.w, acc[i].w);
            }
        }
        __syncthreads();
    }

    const float inv = 1.f / lrow;
    const int b_ = bh >> 3, h = bh & 7;
    float* dst = g_ao + ((size_t)(b_ * SEQ + qi)) * INNER + h * DHEAD;
#pragma unroll
    for (int i = 0; i < 16; i++) {
        float4 o = acc[i];
        o.x *= inv; o.y *= inv; o.z *= inv; o.w *= inv;
        *(float4*)&dst[i * 4] = o;
    }
}

// ============================================================================
extern "C" void kernel_launch(void* const* d_in, const int* in_sizes, int n_in,
                              void* d_out, int out_size)
{
    const float* x    = nullptr;
    const float* wqkv = nullptr;
    const float* wout = nullptr;
    const float* temp = nullptr;
    for (int i = 0; i < n_in; i++) {
        switch (in_sizes[i]) {
            case 4194304: x    = (const float*)d_in[i]; break;
            case 786432:  wqkv = (const float*)d_in[i]; break;
            case 262144:  wout = (const float*)d_in[i]; break;
            case 1:       temp = (const float*)d_in[i]; break;
            default: break;
        }
    }
    float* out = (float*)d_out;

    __nv_bfloat16 *wq_hi, *wq_lo, *wo_hi, *wo_lo;
    float* aoptr;
    cudaGetSymbolAddress((void**)&wq_hi, g_wqkv_hi);
    cudaGetSymbolAddress((void**)&wq_lo, g_wqkv_lo);
    cudaGetSymbolAddress((void**)&wo_hi, g_wout_hi);
    cudaGetSymbolAddress((void**)&wo_lo, g_wout_lo);
    cudaGetSymbolAddress((void**)&aoptr, g_ao);

    wsplit_kernel<<<dim3(48, 16), dim3(32, 32)>>>(wqkv, wq_hi, wq_lo, 3 * INNER);
    wsplit_kernel<<<dim3(16, 16), dim3(32, 32)>>>(wout, wo_hi, wo_lo, INNER);

    gemm_hmma_kernel<<<dim3(12, 64), 256>>>(x, wq_hi, wq_lo, nullptr, 0);
    attn_kernel<<<dim3(8, 64), 128>>>(temp);
    gemm_hmma_kernel<<<dim3(4, 64), 256>>>(aoptr, wo_hi, wo_lo, out, 1);
    (void)out_size;
}

// round 4
// speedup vs baseline: 3.3083x; 2.4344x over previous
#include <cuda_runtime.h>
#include <cuda_bf16.h>
#include <math.h>
#include <stdint.h>

#define NB      8
#define SEQ     1024
#define DIM     512
#define NHEADS  8
#define DHEAD   64
#define INNER   512
#define M_TOT   (NB*SEQ)        /* 8192 */
#define BH      (NB*NHEADS)     /* 64 */

// ---- scratch (allocation-free: __device__ globals) ----
__device__ float g_ao[(size_t)M_TOT*INNER];    // [b*n][h*d] attention output
// pre-split bf16 q/k/v, layout [bh][n][d] (q has exp(temperature) folded in)
__device__ __nv_bfloat16 g_qhi[(size_t)BH*SEQ*DHEAD];
__device__ __nv_bfloat16 g_qlo[(size_t)BH*SEQ*DHEAD];
__device__ __nv_bfloat16 g_khi[(size_t)BH*SEQ*DHEAD];
__device__ __nv_bfloat16 g_klo[(size_t)BH*SEQ*DHEAD];
__device__ __nv_bfloat16 g_vhi[(size_t)BH*SEQ*DHEAD];
__device__ __nv_bfloat16 g_vlo[(size_t)BH*SEQ*DHEAD];
// pre-transposed + split weights: [n][k] bf16
__device__ __nv_bfloat16 g_wqkv_hi[(size_t)3*INNER*DIM];
__device__ __nv_bfloat16 g_wqkv_lo[(size_t)3*INNER*DIM];
__device__ __nv_bfloat16 g_wout_hi[(size_t)DIM*INNER];
__device__ __nv_bfloat16 g_wout_lo[(size_t)DIM*INNER];

// ========================== mma/ldmatrix helpers ===========================
__device__ __forceinline__ uint32_t smem_u32(const void* p) {
    uint32_t a;
    asm("{ .reg .u64 t; cvta.to.shared.u64 t, %1; cvt.u32.u64 %0, t; }" : "=r"(a) : "l"(p));
    return a;
}
__device__ __forceinline__ void ldm_x4(uint32_t* f, uint32_t addr) {
    asm volatile("ldmatrix.sync.aligned.m8n8.x4.shared.b16 {%0,%1,%2,%3}, [%4];"
                 : "=r"(f[0]), "=r"(f[1]), "=r"(f[2]), "=r"(f[3]) : "r"(addr));
}
__device__ __forceinline__ void ldm_x4t(uint32_t* f, uint32_t addr) {
    asm volatile("ldmatrix.sync.aligned.m8n8.x4.trans.shared.b16 {%0,%1,%2,%3}, [%4];"
                 : "=r"(f[0]), "=r"(f[1]), "=r"(f[2]), "=r"(f[3]) : "r"(addr));
}
__device__ __forceinline__ void mma_bf16(float* d, const uint32_t* a, const uint32_t* b) {
    asm volatile("mma.sync.aligned.m16n8k16.row.col.f32.bf16.bf16.f32 "
                 "{%0,%1,%2,%3}, {%4,%5,%6,%7}, {%8,%9}, {%0,%1,%2,%3};"
                 : "+f"(d[0]), "+f"(d[1]), "+f"(d[2]), "+f"(d[3])
                 : "r"(a[0]), "r"(a[1]), "r"(a[2]), "r"(a[3]), "r"(b[0]), "r"(b[1]));
}
__device__ __forceinline__ uint32_t pack_hi(float x, float y) {
    __nv_bfloat162 h = {__float2bfloat16(x), __float2bfloat16(y)};
    return *(uint32_t*)&h;
}
__device__ __forceinline__ uint32_t pack_lo(float x, float y) {
    float rx = x - __bfloat162float(__float2bfloat16(x));
    float ry = y - __bfloat162float(__float2bfloat16(y));
    __nv_bfloat162 l = {__float2bfloat16(rx), __float2bfloat16(ry)};
    return *(uint32_t*)&l;
}

// ============================================================================
// Weight prep: transpose [512][N] fp32 -> [N][512] bf16 (hi, lo split)
// ============================================================================
__global__ void wsplit_kernel(const float* __restrict__ W,
                              __nv_bfloat16* __restrict__ hi,
                              __nv_bfloat16* __restrict__ lo, int N)
{
    __shared__ float t[32][33];
    int n = blockIdx.x * 32 + threadIdx.x;
    int k = blockIdx.y * 32 + threadIdx.y;
    t[threadIdx.y][threadIdx.x] = W[(size_t)k * N + n];
    __syncthreads();
    int n2 = blockIdx.x * 32 + threadIdx.y;
    int k2 = blockIdx.y * 32 + threadIdx.x;
    float v = t[threadIdx.x][threadIdx.y];
    __nv_bfloat16 h = __float2bfloat16(v);
    hi[(size_t)n2 * DIM + k2] = h;
    lo[(size_t)n2 * DIM + k2] = __float2bfloat16(v - __bfloat162float(h));
}

// ============================================================================
// HMMA GEMM (128x128 tile, BK=32, 8 warps 4x2, split-bf16 3-MMA).
// mode 0: epilogue splits+scatters q(scaled)/k/v to bf16 [bh][n][d] buffers.
// mode 1: plain fp32 store to C.
// ============================================================================
#define BK  32
#define PAD 40

__global__ __launch_bounds__(256) void gemm_hmma_kernel(
    const float* __restrict__ A,
    const __nv_bfloat16* __restrict__ Bhi,
    const __nv_bfloat16* __restrict__ Blo,
    float* __restrict__ C, const float* __restrict__ temp, int mode)
{
    __shared__ __nv_bfloat16 sAhi[128 * PAD];
    __shared__ __nv_bfloat16 sAlo[128 * PAD];
    __shared__ __nv_bfloat16 sBhi[128 * PAD];
    __shared__ __nv_bfloat16 sBlo[128 * PAD];

    const int tx   = threadIdx.x;
    const int lane = tx & 31;
    const int wid  = tx >> 5;
    const int wm   = wid >> 1;
    const int wn   = wid & 1;
    const int row0 = blockIdx.y * 128;
    const int col0 = blockIdx.x * 128;

    const uint32_t uAhi = smem_u32(sAhi), uAlo = smem_u32(sAlo);
    const uint32_t uBhi = smem_u32(sBhi), uBlo = smem_u32(sBlo);

    float acc[2][8][4];
#pragma unroll
    for (int i = 0; i < 2; i++)
#pragma unroll
        for (int j = 0; j < 8; j++)
#pragma unroll
            for (int t = 0; t < 4; t++) acc[i][j][t] = 0.f;

    const int a_row  = lane & 15;
    const int a_half = lane >> 4;
    const int b_row  = (lane & 7) + ((lane >> 4) << 3);
    const int b_half = (lane >> 3) & 1;

    for (int kc = 0; kc < DIM; kc += BK) {
#pragma unroll
        for (int t = 0; t < 4; t++) {
            int id = tx + t * 256;
            int r  = id >> 3;
            int c4 = (id & 7) << 2;
            float4 v = *(const float4*)&A[(size_t)(row0 + r) * DIM + kc + c4];
            uint2 hu = make_uint2(pack_hi(v.x, v.y), pack_hi(v.z, v.w));
            uint2 lu = make_uint2(pack_lo(v.x, v.y), pack_lo(v.z, v.w));
            int off = r * PAD + c4;
            *(uint2*)&sAhi[off] = hu;
            *(uint2*)&sAlo[off] = lu;
        }
#pragma unroll
        for (int t = 0; t < 2; t++) {
            int id = tx + t * 256;
            int r  = id >> 2;
            int c8 = (id & 3) << 3;
            size_t go = (size_t)(col0 + r) * DIM + kc + c8;
            int off = r * PAD + c8;
            *(uint4*)&sBhi[off] = *(const uint4*)&Bhi[go];
            *(uint4*)&sBlo[off] = *(const uint4*)&Blo[go];
        }
        __syncthreads();

#pragma unroll
        for (int kk = 0; kk < 2; kk++) {
            uint32_t afh[2][4], afl[2][4];
#pragma unroll
            for (int mf = 0; mf < 2; mf++) {
                uint32_t boff = (uint32_t)((wm * 32 + mf * 16 + a_row) * PAD + kk * 16) * 2
                              + a_half * 16;
                ldm_x4(afh[mf], uAhi + boff);
                ldm_x4(afl[mf], uAlo + boff);
            }
            uint32_t bfh[8][2], bfl[8][2];
#pragma unroll
            for (int nf2 = 0; nf2 < 4; nf2++) {
                uint32_t boff = (uint32_t)((wn * 64 + nf2 * 16 + b_row) * PAD + kk * 16) * 2
                              + b_half * 16;
                uint32_t th[4], tl[4];
                ldm_x4(th, uBhi + boff);
                ldm_x4(tl, uBlo + boff);
                bfh[nf2*2][0] = th[0]; bfh[nf2*2][1] = th[1];
                bfh[nf2*2+1][0] = th[2]; bfh[nf2*2+1][1] = th[3];
                bfl[nf2*2][0] = tl[0]; bfl[nf2*2][1] = tl[1];
                bfl[nf2*2+1][0] = tl[2]; bfl[nf2*2+1][1] = tl[3];
            }
#pragma unroll
            for (int mf = 0; mf < 2; mf++)
#pragma unroll
                for (int nf = 0; nf < 8; nf++) {
                    mma_bf16(acc[mf][nf], afh[mf], bfh[nf]);
                    mma_bf16(acc[mf][nf], afh[mf], bfl[nf]);
                    mma_bf16(acc[mf][nf], afl[mf], bfh[nf]);
                }
        }
        __syncthreads();
    }

    const float sc = (mode == 0) ? __expf(*temp) : 1.f;
#pragma unroll
    for (int mf = 0; mf < 2; mf++) {
        int m_base = row0 + wm * 32 + mf * 16 + (lane >> 2);
#pragma unroll
        for (int nf = 0; nf < 8; nf++) {
            int c = col0 + wn * 64 + nf * 8 + 2 * (lane & 3);
            float2 v0 = make_float2(acc[mf][nf][0], acc[mf][nf][1]);
            float2 v1 = make_float2(acc[mf][nf][2], acc[mf][nf][3]);
            if (mode == 1) {
                *(float2*)&C[(size_t)m_base * DIM + c]       = v0;
                *(float2*)&C[(size_t)(m_base + 8) * DIM + c] = v1;
            } else {
                int which = c >> 9;
                int inner = c & 511;
                int h     = inner >> 6;
                int d     = inner & 63;
                __nv_bfloat16 *bh_, *bl_;
                if (which == 0) {
                    v0.x *= sc; v0.y *= sc; v1.x *= sc; v1.y *= sc;
                    bh_ = g_qhi; bl_ = g_qlo;
                } else if (which == 1) { bh_ = g_khi; bl_ = g_klo; }
                else                   { bh_ = g_vhi; bl_ = g_vlo; }
                int b0 = m_base >> 10, n0 = m_base & 1023;
                size_t off0 = ((size_t)((b0 * NHEADS + h) * SEQ + n0)) * DHEAD + d;
                *(uint32_t*)&bh_[off0] = pack_hi(v0.x, v0.y);
                *(uint32_t*)&bl_[off0] = pack_lo(v0.x, v0.y);
                int m1 = m_base + 8;
                int b1 = m1 >> 10, n1 = m1 & 1023;
                size_t off1 = ((size_t)((b1 * NHEADS + h) * SEQ + n1)) * DHEAD + d;
                *(uint32_t*)&bh_[off1] = pack_hi(v1.x, v1.y);
                *(uint32_t*)&bl_[off1] = pack_lo(v1.x, v1.y);
            }
        }
    }
}

// ============================================================================
// Flash attention on HMMA. CTA = 128 thr (4 warps), 64 q-rows; K-tiles of 64.
// Split-bf16 3-MMA for QK and PV; online softmax in registers.
// ============================================================================
#define KST 72   /* smem row stride (bf16) for 64-wide tiles */

__global__ __launch_bounds__(128) void attn_hmma_kernel()
{
    __shared__ __nv_bfloat16 sKh[64 * KST];
    __shared__ __nv_bfloat16 sKl[64 * KST];
    __shared__ __nv_bfloat16 sVh[64 * KST];
    __shared__ __nv_bfloat16 sVl[64 * KST];

    const int tx   = threadIdx.x;
    const int lane = tx & 31;
    const int wq   = tx >> 5;              // warp -> 16 q rows
    const int bh   = blockIdx.y;
    const int q0   = blockIdx.x * 64;
    const size_t base = (size_t)bh * SEQ * DHEAD;

    const uint32_t uKh = smem_u32(sKh), uKl = smem_u32(sKl);
    const uint32_t uVh = smem_u32(sVh), uVl = smem_u32(sVl);

    // ---- stage Q tile (64 rows) into sKh/sKl, pull a-frags to registers ----
#pragma unroll
    for (int t = 0; t < 4; t++) {
        int id = tx + t * 128;
        int r = id >> 3, c8 = (id & 7) << 3;
        *(uint4*)&sKh[r * KST + c8] = *(const uint4*)&g_qhi[base + (size_t)(q0 + r) * DHEAD + c8];
        *(uint4*)&sKl[r * KST + c8] = *(const uint4*)&g_qlo[base + (size_t)(q0 + r) * DHEAD + c8];
    }
    __syncthreads();

    const int a_row  = lane & 15;
    const int a_half = lane >> 4;
    uint32_t qh[4][4], ql[4][4];
#pragma unroll
    for (int ks = 0; ks < 4; ks++) {
        uint32_t boff = (uint32_t)((wq * 16 + a_row) * KST + ks * 16) * 2 + a_half * 16;
        ldm_x4(qh[ks], uKh + boff);
        ldm_x4(ql[ks], uKl + boff);
    }
    __syncthreads();

    float oacc[8][4];
#pragma unroll
    for (int i = 0; i < 8; i++)
#pragma unroll
        for (int j = 0; j < 4; j++) oacc[i][j] = 0.f;
    float m0 = -INFINITY, m1 = -INFINITY, l0 = 0.f, l1 = 0.f;

    const int b_row  = (lane & 7) + ((lane >> 4) << 3);
    const int b_half = (lane >> 3) & 1;
    const int v_mat  = lane >> 3;          // trans ldmatrix lane mapping
    const int v_row  = lane & 7;
    const int ra     = lane >> 2;          // this thread's first q row-in-16
    const int c_in   = 2 * (lane & 3);

    for (int kt = 0; kt < 16; kt++) {
        // ---- cooperative K/V tile load (bf16 copies) ----
#pragma unroll
        for (int t = 0; t < 4; t++) {
            int id = tx + t * 128;
            int r = id >> 3, c8 = (id & 7) << 3;
            size_t g = base + (size_t)(kt * 64 + r) * DHEAD + c8;
            int off = r * KST + c8;
            *(uint4*)&sKh[off] = *(const uint4*)&g_khi[g];
            *(uint4*)&sKl[off] = *(const uint4*)&g_klo[g];
            *(uint4*)&sVh[off] = *(const uint4*)&g_vhi[g];
            *(uint4*)&sVl[off] = *(const uint4*)&g_vlo[g];
        }
        __syncthreads();

        // ---- S = Q K^T (split 3-MMA) ----
        float sacc[8][4];
#pragma unroll
        for (int i = 0; i < 8; i++)
#pragma unroll
            for (int j = 0; j < 4; j++) sacc[i][j] = 0.f;
#pragma unroll
        for (int nf2 = 0; nf2 < 4; nf2++) {
#pragma unroll
            for (int ks = 0; ks < 4; ks++) {
                uint32_t kh[4], kl[4];
                uint32_t boff = (uint32_t)((nf2 * 16 + b_row) * KST + ks * 16) * 2 + b_half * 16;
                ldm_x4(kh, uKh + boff);
                ldm_x4(kl, uKl + boff);
                mma_bf16(sacc[2*nf2],   qh[ks], kh);
                mma_bf16(sacc[2*nf2],   qh[ks], kl);
                mma_bf16(sacc[2*nf2],   ql[ks], kh);
                mma_bf16(sacc[2*nf2+1], qh[ks], kh + 2);
                mma_bf16(sacc[2*nf2+1], qh[ks], kl + 2);
                mma_bf16(sacc[2*nf2+1], ql[ks], kh + 2);
            }
        }

        // ---- diagonal mask (only the tile on the diagonal) ----
        if (kt == blockIdx.x) {
            int row_a = q0 + wq * 16 + ra;
            int row_b = row_a + 8;
#pragma unroll
            for (int nf = 0; nf < 8; nf++) {
                int col = kt * 64 + nf * 8 + c_in;
                if (col     == row_a) sacc[nf][0] = -INFINITY;
                if (col + 1 == row_a) sacc[nf][1] = -INFINITY;
                if (col     == row_b) sacc[nf][2] = -INFINITY;
                if (col + 1 == row_b) sacc[nf][3] = -INFINITY;
            }
        }

        // ---- online softmax ----
        float mt0 = -INFINITY, mt1 = -INFINITY;
#pragma unroll
        for (int nf = 0; nf < 8; nf++) {
            mt0 = fmaxf(mt0, fmaxf(sacc[nf][0], sacc[nf][1]));
            mt1 = fmaxf(mt1, fmaxf(sacc[nf][2], sacc[nf][3]));
        }
        mt0 = fmaxf(mt0, __shfl_xor_sync(0xffffffffu, mt0, 1));
        mt0 = fmaxf(mt0, __shfl_xor_sync(0xffffffffu, mt0, 2));
        mt1 = fmaxf(mt1, __shfl_xor_sync(0xffffffffu, mt1, 1));
        mt1 = fmaxf(mt1, __shfl_xor_sync(0xffffffffu, mt1, 2));

        float mn0 = fmaxf(m0, mt0), mn1 = fmaxf(m1, mt1);
        float cr0 = __expf(m0 - mn0), cr1 = __expf(m1 - mn1);
        float ls0 = 0.f, ls1 = 0.f;
#pragma unroll
        for (int nf = 0; nf < 8; nf++) {
            float p0 = __expf(sacc[nf][0] - mn0);
            float p1 = __expf(sacc[nf][1] - mn0);
            float p2 = __expf(sacc[nf][2] - mn1);
            float p3 = __expf(sacc[nf][3] - mn1);
            ls0 += p0 + p1; ls1 += p2 + p3;
            sacc[nf][0] = p0; sacc[nf][1] = p1; sacc[nf][2] = p2; sacc[nf][3] = p3;
        }
        l0 = l0 * cr0 + ls0;  l1 = l1 * cr1 + ls1;
        m0 = mn0;             m1 = mn1;
#pragma unroll
        for (int nf = 0; nf < 8; nf++) {
            oacc[nf][0] *= cr0; oacc[nf][1] *= cr0;
            oacc[nf][2] *= cr1; oacc[nf][3] *= cr1;
        }

        // ---- O += P V (split 3-MMA; V b-frags via ldmatrix.trans) ----
#pragma unroll
        for (int kb = 0; kb < 4; kb++) {
            uint32_t pa_h[4], pa_l[4];
            pa_h[0] = pack_hi(sacc[2*kb][0],   sacc[2*kb][1]);
            pa_h[1] = pack_hi(sacc[2*kb][2],   sacc[2*kb][3]);
            pa_h[2] = pack_hi(sacc[2*kb+1][0], sacc[2*kb+1][1]);
            pa_h[3] = pack_hi(sacc[2*kb+1][2], sacc[2*kb+1][3]);
            pa_l[0] = pack_lo(sacc[2*kb][0],   sacc[2*kb][1]);
            pa_l[1] = pack_lo(sacc[2*kb][2],   sacc[2*kb][3]);
            pa_l[2] = pack_lo(sacc[2*kb+1][0], sacc[2*kb+1][1]);
            pa_l[3] = pack_lo(sacc[2*kb+1][2], sacc[2*kb+1][3]);
#pragma unroll
            for (int nf2 = 0; nf2 < 4; nf2++) {
                // four 8x8 tiles: (k0+{0,8}) x (d0+{0,8}), transposed on load
                uint32_t boff = (uint32_t)((kb * 16 + (v_mat & 1) * 8 + v_row) * KST
                                           + nf2 * 16 + (v_mat >> 1) * 8) * 2;
                uint32_t vh[4], vl[4];
                ldm_x4t(vh, uVh + boff);
                ldm_x4t(vl, uVl + boff);
                mma_bf16(oacc[2*nf2],   pa_h, vh);
                mma_bf16(oacc[2*nf2],   pa_h, vl);
                mma_bf16(oacc[2*nf2],   pa_l, vh);
                mma_bf16(oacc[2*nf2+1], pa_h, vh + 2);
                mma_bf16(oacc[2*nf2+1], pa_h, vl + 2);
                mma_bf16(oacc[2*nf2+1], pa_l, vh + 2);
            }
        }
        __syncthreads();
    }

    // ---- finalize: reduce l across quad, normalize, store ----
    l0 += __shfl_xor_sync(0xffffffffu, l0, 1);
    l0 += __shfl_xor_sync(0xffffffffu, l0, 2);
    l1 += __shfl_xor_sync(0xffffffffu, l1, 1);
    l1 += __shfl_xor_sync(0xffffffffu, l1, 2);
    float inv0 = 1.f / l0, inv1 = 1.f / l1;

    const int b_ = bh >> 3, h = bh & 7;
    int row_a = q0 + wq * 16 + ra;
#pragma unroll
    for (int nf = 0; nf < 8; nf++) {
        int col = h * DHEAD + nf * 8 + c_in;
        *(float2*)&g_ao[(size_t)(b_ * SEQ + row_a) * INNER + col] =
            make_float2(oacc[nf][0] * inv0, oacc[nf][1] * inv0);
        *(float2*)&g_ao[(size_t)(b_ * SEQ + row_a + 8) * INNER + col] =
            make_float2(oacc[nf][2] * inv1, oacc[nf][3] * inv1);
    }
}

// ============================================================================
extern "C" void kernel_launch(void* const* d_in, const int* in_sizes, int n_in,
                              void* d_out, int out_size)
{
    const float* x    = nullptr;
    const float* wqkv = nullptr;
    const float* wout = nullptr;
    const float* temp = nullptr;
    for (int i = 0; i < n_in; i++) {
        switch (in_sizes[i]) {
            case 4194304: x    = (const float*)d_in[i]; break;
            case 786432:  wqkv = (const float*)d_in[i]; break;
            case 262144:  wout = (const float*)d_in[i]; break;
            case 1:       temp = (const float*)d_in[i]; break;
            default: break;
        }
    }
    float* out = (float*)d_out;

    __nv_bfloat16 *wq_hi, *wq_lo, *wo_hi, *wo_lo;
    float* aoptr;
    cudaGetSymbolAddress((void**)&wq_hi, g_wqkv_hi);
    cudaGetSymbolAddress((void**)&wq_lo, g_wqkv_lo);
    cudaGetSymbolAddress((void**)&wo_hi, g_wout_hi);
    cudaGetSymbolAddress((void**)&wo_lo, g_wout_lo);
    cudaGetSymbolAddress((void**)&aoptr, g_ao);

    wsplit_kernel<<<dim3(48, 16), dim3(32, 32)>>>(wqkv, wq_hi, wq_lo, 3 * INNER);
    wsplit_kernel<<<dim3(16, 16), dim3(32, 32)>>>(wout, wo_hi, wo_lo, INNER);

    gemm_hmma_kernel<<<dim3(12, 64), 256>>>(x, wq_hi, wq_lo, nullptr, temp, 0);
    attn_hmma_kernel<<<dim3(16, 64), 128>>>();
    gemm_hmma_kernel<<<dim3(4, 64), 256>>>(aoptr, wo_hi, wo_lo, out, temp, 1);
    (void)out_size;
}